// round 4
// baseline (speedup 1.0000x reference)
#include <cuda_runtime.h>
#include <stdint.h>

#define NB     8
#define NF4    65536              // float4 groups per sample (512*512/4)
#define NBINS  2048
#define GRID   592                // 4 blocks/SM * 148 SMs (all-resident on 152 too)
#define BPS    74                 // blocks per sample (74*8 = 592)
#define STRIDE (BPS * 256)        // 18944 groups per sample-iteration
#define ITER   4                  // ceil(65536 / 18944)

__device__ uint4    g_pk   [NB * NF4];       // 8MB packed bf16x2 scratch (L2-resident)
__device__ unsigned g_hist1[2][NB][NBINS];
__device__ unsigned g_cnt2 [2][NB][32];
__device__ float    g_Sab  [2][NB];
__device__ unsigned g_count[NB];
__device__ int      g_bin1 [2][NB];
__device__ unsigned g_cab  [2][NB];
__device__ unsigned g_bar  [4];              // monotonic epoch counters (never reset)

__device__ __forceinline__ unsigned f2bf(float f) {   // RNE f32->bf16 bits (nonneg finite)
    unsigned u = __float_as_uint(f);
    return (u + 0x7FFFu + ((u >> 16) & 1u)) >> 16;
}
__device__ __forceinline__ float bf2f(unsigned b) { return __uint_as_float(b << 16); }
__device__ __forceinline__ float pget(const float4& v, int p) { return p == 0 ? v.x : p == 1 ? v.y : p == 2 ? v.z : v.w; }
__device__ __forceinline__ int   tget(const int4&   v, int p) { return p == 0 ? v.x : p == 1 ? v.y : p == 2 ? v.z : v.w; }

__device__ __forceinline__ void grid_barrier(int id) {
    __syncthreads();
    if (threadIdx.x == 0) {
        __threadfence();
        unsigned old = atomicAdd(&g_bar[id], 1u);
        unsigned target = old - (old % GRID) + GRID;
        while (*((volatile unsigned*)&g_bar[id]) < target) __nanosleep(128);
        __threadfence();
    }
    __syncthreads();
}

__global__ void __launch_bounds__(256, 4)
kFused(const float4* __restrict__ img, const float4* __restrict__ alp,
       const float4* __restrict__ prd, const int4*   __restrict__ tri,
       const float4* __restrict__ fg,  const float4* __restrict__ bg,
       float* out)
{
    __shared__ unsigned sh[2][NBINS];        // 16KB histograms / reloaded global hist
    __shared__ unsigned wt[8];
    __shared__ int      s_bin1[2];
    __shared__ unsigned s_tie[2][32];
    __shared__ unsigned s_redu[8];
    __shared__ float    sr0[8], sr1[8];

    const int t   = threadIdx.x;
    const int l   = t & 31, w = t >> 5;
    const int blk = blockIdx.x;
    const int b   = blk / BPS;               // sample id
    const int lb  = blk - b * BPS;
    const int cb  = b * 3 * NF4;             // 3-channel tensor base

    for (int i = t; i < 2 * NBINS; i += 256) ((unsigned*)sh)[i] = 0u;
    if (blk == 0 && t == 0) out[0] = 0.0f;
    __syncthreads();

    // ---- phase 1: compute d/dc, pack to scratch, level-1 histogram ---------
    unsigned cnt = 0;
    const float inv255 = 1.0f / 255.0f;
#pragma unroll
    for (int j = 0; j < ITER; j++) {
        int gl = lb * 256 + t + j * STRIDE;  // interleaved: zero overlap, coalesced
        if (gl >= NF4) break;                // only last iter partially full (uniform per warp)
        int g = b * NF4 + gl;
        int4   tv = tri[g];
        float4 av = alp[g], pv = prd[g];
        float4 i0 = img[cb + gl], i1 = img[cb + NF4 + gl], i2 = img[cb + 2 * NF4 + gl];
        float4 f0 = fg [cb + gl], f1 = fg [cb + NF4 + gl], f2 = fg [cb + 2 * NF4 + gl];
        float4 g0 = bg [cb + gl], g1 = bg [cb + NF4 + gl], g2 = bg [cb + 2 * NF4 + gl];
        unsigned pk[4];
#pragma unroll
        for (int p = 0; p < 4; p++) {
            bool u = (tget(tv, p) == 128);
            float pr = pget(pv, p), q = 1.0f - pr;
            float d = 0.0f, dc = 0.0f;
            if (u) {
                d  = fabsf(pget(av, p) * inv255 - pr);
                dc = fabsf(pget(i0, p) - (pget(f0, p) * pr + q * pget(g0, p)))
                   + fabsf(pget(i1, p) - (pget(f1, p) * pr + q * pget(g1, p)))
                   + fabsf(pget(i2, p) - (pget(f2, p) * pr + q * pget(g2, p)));
                cnt++;
            }
            unsigned kd = f2bf(d), kc = f2bf(dc);
            pk[p] = kd | (kc << 16);
            int bd = u ? (int)(kd >> 5) : -1;
            int bc = u ? (int)(kc >> 5) : -2;
            unsigned m1 = __match_any_sync(0xffffffffu, bd);
            if (u && (int)(__ffs(m1) - 1) == l) atomicAdd(&sh[0][bd], (unsigned)__popc(m1));
            unsigned m2 = __match_any_sync(0xffffffffu, bc);
            if (u && (int)(__ffs(m2) - 1) == l) atomicAdd(&sh[1][bc], (unsigned)__popc(m2));
        }
        g_pk[g] = make_uint4(pk[0], pk[1], pk[2], pk[3]);
    }
    for (int o = 16; o; o >>= 1) cnt += __shfl_down_sync(0xffffffffu, cnt, o);
    if (l == 0) s_redu[w] = cnt;
    __syncthreads();
    if (t == 0) {
        unsigned tot = 0;
#pragma unroll
        for (int i = 0; i < 8; i++) tot += s_redu[i];
        atomicAdd(&g_count[b], tot);
    }
    for (int i = t; i < NBINS; i += 256) {
        unsigned c0 = sh[0][i]; if (c0) atomicAdd(&g_hist1[0][b][i], c0);
        unsigned c1 = sh[1][i]; if (c1) atomicAdd(&g_hist1[1][b][i], c1);
    }

    grid_barrier(0);

    // ---- phase 1.5: every block selects level-1 bin for its sample ---------
    unsigned count = g_count[b];
    int k = (int)floorf((float)count * 0.7f);

    for (int i = t; i < NBINS; i += 256) { sh[0][i] = g_hist1[0][b][i]; sh[1][i] = g_hist1[1][b][i]; }
    if (t < 2) s_bin1[t] = 1 << 29;          // sentinel when k<=0
    __syncthreads();

#pragma unroll
    for (int a = 0; a < 2; a++) {
        unsigned loc = 0;
#pragma unroll
        for (int jj = 0; jj < 8; jj++) loc += sh[a][t * 8 + jj];
        unsigned s = loc;
#pragma unroll
        for (int o = 1; o < 32; o <<= 1) {   // inclusive suffix scan within warp
            unsigned v = __shfl_down_sync(0xffffffffu, s, o);
            if (l + o < 32) s += v;
        }
        if (l == 0) wt[w] = s;
        __syncthreads();
        unsigned wsuf = 0;
        for (int w2 = w + 1; w2 < 8; w2++) wsuf += wt[w2];
        unsigned acc = wsuf + (s - loc);     // strictly above this thread's bins
        if (k > 0) {
#pragma unroll
            for (int jj = 7; jj >= 0; jj--) {
                int i = t * 8 + jj;
                unsigned c = sh[a][i];
                if (c && acc < (unsigned)k && acc + c >= (unsigned)k) {
                    s_bin1[a] = i;
                    g_bin1[a][b] = i;        // duplicate identical writes: benign
                    g_cab[a][b]  = acc;
                }
                acc += c;
            }
        }
        __syncthreads();
    }

    // ---- phase 2: re-walk packed scratch (L2-hot), sum-above + tie count ---
    for (int i = t; i < 64; i += 256) ((unsigned*)s_tie)[i] = 0u;
    __syncthreads();

    const int b1d = s_bin1[0], b1c = s_bin1[1];
    float s0 = 0.0f, s1 = 0.0f;
#pragma unroll
    for (int j = 0; j < ITER; j++) {
        int gl = lb * 256 + t + j * STRIDE;
        if (gl >= NF4) break;
        uint4 pv4 = g_pk[b * NF4 + gl];
        unsigned pk4[4] = { pv4.x, pv4.y, pv4.z, pv4.w };
#pragma unroll
        for (int p = 0; p < 4; p++) {
            unsigned kd = pk4[p] & 0xFFFFu, kc = pk4[p] >> 16;
            int bd = (int)(kd >> 5), bc = (int)(kc >> 5);
            if (bd > b1d)       s0 += bf2f(kd);
            else if (bd == b1d) atomicAdd(&s_tie[0][kd & 31u], 1u);
            if (bc > b1c)       s1 += bf2f(kc);
            else if (bc == b1c) atomicAdd(&s_tie[1][kc & 31u], 1u);
        }
    }
    for (int o = 16; o; o >>= 1) {
        s0 += __shfl_down_sync(0xffffffffu, s0, o);
        s1 += __shfl_down_sync(0xffffffffu, s1, o);
    }
    if (l == 0) { sr0[w] = s0; sr1[w] = s1; }
    __syncthreads();
    if (t == 0) {
        float a0 = 0.f, a1 = 0.f;
#pragma unroll
        for (int i = 0; i < 8; i++) { a0 += sr0[i]; a1 += sr1[i]; }
        if (a0 != 0.f) atomicAdd(&g_Sab[0][b], a0);
        if (a1 != 0.f) atomicAdd(&g_Sab[1][b], a1);
    }
    if (t < 64) {
        unsigned c = ((unsigned*)s_tie)[t];
        if (c) atomicAdd(&g_cnt2[t >> 5][b][t & 31], c);
    }

    grid_barrier(1);

    // ---- phase 3: 16 units finalize ----------------------------------------
    if (blk < 16 && t == 0) {
        int a = blk >> 3, bb = blk & 7;
        unsigned cc = g_count[bb];
        int kk = (int)floorf((float)cc * 0.7f);
        if (kk > 0) {
            unsigned acc = g_cab[a][bb];
            float S = g_Sab[a][bb];
            int bin1 = g_bin1[a][bb];
            for (int i = 31; i >= 0; i--) {
                unsigned c = g_cnt2[a][bb][i];
                if (!c) continue;
                float v = bf2f((unsigned)((bin1 << 5) | i));   // exact bf16 code
                if (acc + c >= (unsigned)kk) { S += (float)(kk - (int)acc) * v; break; }
                acc += c; S += (float)c * v;
            }
            atomicAdd(out, 0.0625f * (S / ((float)kk + 1e-6f)));  // 0.5*loss/8
        }
    }

    grid_barrier(2);

    // ---- cleanup for next graph replay -------------------------------------
    {
        int gid = blk * 256 + t;
        if (gid < 2 * NB * NBINS) ((unsigned*)g_hist1)[gid] = 0u;
        if (gid < 2 * NB * 32)    ((unsigned*)g_cnt2)[gid]  = 0u;
        if (gid < 2 * NB)         ((float*)g_Sab)[gid]      = 0.f;
        if (gid < NB)             g_count[gid]              = 0u;
        // g_bar intentionally NOT reset (monotonic epochs)
    }
}

extern "C" void kernel_launch(void* const* d_in, const int* in_sizes, int n_in,
                              void* d_out, int out_size) {
    const float4* img = (const float4*)d_in[0];
    const float4* alp = (const float4*)d_in[1];
    const float4* prd = (const float4*)d_in[2];
    const int4*   tri = (const int4*)  d_in[3];
    const float4* fg  = (const float4*)d_in[4];
    const float4* bg  = (const float4*)d_in[5];
    kFused<<<GRID, 256>>>(img, alp, prd, tri, fg, bg, (float*)d_out);
}